// round 6
// baseline (speedup 1.0000x reference)
#include <cuda_runtime.h>
#include <cuda_bf16.h>
#include <stdint.h>

#define BATCHN  16
#define TLEN    128
#define NROWS   2048          // BATCH*TLEN
#define DIM     1024
#define VOCAB   32000
#define CVOCAB  120
#define SLEN    400
#define AGENDA  100
#define CTX     300
#define OUTC    (VOCAB + CVOCAB)   // 32120
#define PAD_IDX 1

// ---- device scratch (no allocation allowed) ----
__device__ float g_pcopy[NROWS];
__device__ float g_rowsum[NROWS];
__device__ float g_scale[NROWS];

// ============================================================
// Kernel 1: p_copy = sigmoid(hidden @ W_copy^T + b_copy); zero rowsum;
//           write p_copy tail of output if present.
// ============================================================
__global__ void prep_kernel(const float* __restrict__ hidden,
                            const float* __restrict__ Wc,
                            const float* __restrict__ bc,
                            float* __restrict__ out, long long out_size) {
    int warp = (blockIdx.x * blockDim.x + threadIdx.x) >> 5;
    int lane = threadIdx.x & 31;
    if (warp >= NROWS) return;
    const float* h = hidden + (long long)warp * DIM;
    float s = 0.f;
#pragma unroll
    for (int j = 0; j < DIM / 32; ++j)
        s += h[j * 32 + lane] * Wc[j * 32 + lane];
#pragma unroll
    for (int o = 16; o > 0; o >>= 1)
        s += __shfl_down_sync(0xffffffffu, s, o);
    if (lane == 0) {
        float p = 1.f / (1.f + __expf(-(s + bc[0])));
        g_pcopy[warp]  = p;
        g_rowsum[warp] = 0.f;
        long long base = (long long)NROWS * OUTC;
        if (out_size >= base + NROWS) out[base + warp] = p;
    }
}

// ============================================================
// Kernel 2: copy_prob[t,b,:] = sum_a (attn[row,300+a]*p_copy[row]) * src_map[a,b,:]
// One block per row (row = t*16 + b).
// ============================================================
__global__ void copy_kernel(const float* __restrict__ attn,
                            const float* __restrict__ src_map,
                            float* __restrict__ out) {
    int row = blockIdx.x;
    int b   = row & (BATCHN - 1);
    __shared__ float ma[AGENDA];
    float p = g_pcopy[row];
    int t = threadIdx.x;
    if (t < AGENDA) ma[t] = attn[(long long)row * SLEN + CTX + t] * p;
    __syncthreads();
    if (t < CVOCAB) {
        float s = 0.f;
        const float* sm = src_map + b * CVOCAB + t;
#pragma unroll 4
        for (int a = 0; a < AGENDA; ++a)
            s += ma[a] * sm[a * (BATCHN * CVOCAB)];
        out[(long long)row * OUTC + VOCAB + t] = s;
    }
}

// ============================================================
// Kernel 3: GEMM logits = hidden @ W^T + b, fused epilogue:
//           e = exp(logit) (0 at PAD col), write e into out, atomic row sums.
// 2-limb bf16 split (3 MMAs) for fp32-class accuracy on mma.sync.m16n8k16.
// ============================================================
#define BM 128
#define BN 128
#define BK 32
#define KP 20   // smem row stride in bf16-PAIRS (uint32): 40 bf16 (32 used + pad)

__device__ __forceinline__ void mma16816(float d[4],
                                         uint32_t a0, uint32_t a1, uint32_t a2, uint32_t a3,
                                         uint32_t b0, uint32_t b1) {
    asm volatile(
        "mma.sync.aligned.m16n8k16.row.col.f32.bf16.bf16.f32 "
        "{%0,%1,%2,%3}, {%4,%5,%6,%7}, {%8,%9}, {%0,%1,%2,%3};\n"
        : "+f"(d[0]), "+f"(d[1]), "+f"(d[2]), "+f"(d[3])
        : "r"(a0), "r"(a1), "r"(a2), "r"(a3), "r"(b0), "r"(b1));
}

__device__ __forceinline__ void cvt_pair(float x, float y, uint32_t& hi, uint32_t& lo) {
    __nv_bfloat16 hx = __float2bfloat16_rn(x);
    __nv_bfloat16 hy = __float2bfloat16_rn(y);
    __nv_bfloat162 h = __halves2bfloat162(hx, hy);
    __nv_bfloat162 l = __floats2bfloat162_rn(x - __bfloat162float(hx),
                                             y - __bfloat162float(hy));
    hi = *reinterpret_cast<uint32_t*>(&h);
    lo = *reinterpret_cast<uint32_t*>(&l);
}

__global__ __launch_bounds__(256, 1)
void gemm_kernel(const float* __restrict__ A,     // hidden [2048][1024]
                 const float* __restrict__ W,     // [32000][1024]
                 const float* __restrict__ bias,  // [32000]
                 float* __restrict__ out) {
    __shared__ uint32_t Ah[BM * KP], Al[BM * KP];
    __shared__ uint32_t Bh[BN * KP], Bl[BN * KP];
    __shared__ float sRow[BM];

    const int tid  = threadIdx.x;
    const int warp = tid >> 5, lane = tid & 31;
    const int wm = warp & 3;      // 4 m-groups of 32 rows
    const int wn = warp >> 2;     // 2 n-groups of 64 cols
    const int g  = lane >> 2, t4 = lane & 3;
    const int m0 = blockIdx.y * BM;
    const int n0 = blockIdx.x * BN;

    float acc[2][8][4];
#pragma unroll
    for (int mi = 0; mi < 2; ++mi)
#pragma unroll
        for (int ni = 0; ni < 8; ++ni)
#pragma unroll
            for (int c = 0; c < 4; ++c) acc[mi][ni][c] = 0.f;

    const float4* A4 = reinterpret_cast<const float4*>(A) + (long long)m0 * (DIM / 4);
    const float4* B4 = reinterpret_cast<const float4*>(W) + (long long)n0 * (DIM / 4);

    // prologue global loads (k-chunk 0): 4 float4 from A tile + 4 from B tile per thread
    float4 ra[4], rb[4];
#pragma unroll
    for (int i = 0; i < 4; ++i) {
        int idx = tid + i * 256;
        int row = idx >> 3, c4 = idx & 7;
        ra[i] = A4[(long long)row * (DIM / 4) + c4];
        rb[i] = B4[(long long)row * (DIM / 4) + c4];
    }

    for (int kc = 0; kc < DIM / BK; ++kc) {
        // convert fp32 -> (hi,lo) bf16 limbs and store to smem
#pragma unroll
        for (int i = 0; i < 4; ++i) {
            int idx = tid + i * 256;
            int row = idx >> 3, c4 = idx & 7;
            uint32_t h0, l0, h1, l1;
            cvt_pair(ra[i].x, ra[i].y, h0, l0);
            cvt_pair(ra[i].z, ra[i].w, h1, l1);
            Ah[row * KP + c4 * 2]     = h0;  Al[row * KP + c4 * 2]     = l0;
            Ah[row * KP + c4 * 2 + 1] = h1;  Al[row * KP + c4 * 2 + 1] = l1;
            cvt_pair(rb[i].x, rb[i].y, h0, l0);
            cvt_pair(rb[i].z, rb[i].w, h1, l1);
            Bh[row * KP + c4 * 2]     = h0;  Bl[row * KP + c4 * 2]     = l0;
            Bh[row * KP + c4 * 2 + 1] = h1;  Bl[row * KP + c4 * 2 + 1] = l1;
        }
        __syncthreads();

        // prefetch next k-chunk while MMAs run
        if (kc + 1 < DIM / BK) {
            int koff = (kc + 1) * (BK / 4);
#pragma unroll
            for (int i = 0; i < 4; ++i) {
                int idx = tid + i * 256;
                int row = idx >> 3, c4 = idx & 7;
                ra[i] = A4[(long long)row * (DIM / 4) + koff + c4];
                rb[i] = B4[(long long)row * (DIM / 4) + koff + c4];
            }
        }

#pragma unroll
        for (int kk = 0; kk < 2; ++kk) {
            const int kp = kk * 8;
            uint32_t ah[2][4], al[2][4];
#pragma unroll
            for (int mi = 0; mi < 2; ++mi) {
                int r = wm * 32 + mi * 16 + g;
                ah[mi][0] = Ah[r * KP + t4 + kp];
                ah[mi][1] = Ah[(r + 8) * KP + t4 + kp];
                ah[mi][2] = Ah[r * KP + t4 + 4 + kp];
                ah[mi][3] = Ah[(r + 8) * KP + t4 + 4 + kp];
                al[mi][0] = Al[r * KP + t4 + kp];
                al[mi][1] = Al[(r + 8) * KP + t4 + kp];
                al[mi][2] = Al[r * KP + t4 + 4 + kp];
                al[mi][3] = Al[(r + 8) * KP + t4 + 4 + kp];
            }
#pragma unroll
            for (int ni = 0; ni < 8; ++ni) {
                int nb = wn * 64 + ni * 8 + g;
                uint32_t bh0 = Bh[nb * KP + t4 + kp];
                uint32_t bh1 = Bh[nb * KP + t4 + 4 + kp];
                uint32_t bl0 = Bl[nb * KP + t4 + kp];
                uint32_t bl1 = Bl[nb * KP + t4 + 4 + kp];
#pragma unroll
                for (int mi = 0; mi < 2; ++mi) {
                    mma16816(acc[mi][ni], ah[mi][0], ah[mi][1], ah[mi][2], ah[mi][3], bh0, bh1);
                    mma16816(acc[mi][ni], ah[mi][0], ah[mi][1], ah[mi][2], ah[mi][3], bl0, bl1);
                    mma16816(acc[mi][ni], al[mi][0], al[mi][1], al[mi][2], al[mi][3], bh0, bh1);
                }
            }
        }
        __syncthreads();
    }

    // ---- fused epilogue: bias, PAD mask, exp, store e, row sums ----
    if (tid < BM) sRow[tid] = 0.f;
    __syncthreads();

    float rs[2][2] = {{0.f, 0.f}, {0.f, 0.f}};
#pragma unroll
    for (int mi = 0; mi < 2; ++mi) {
#pragma unroll
        for (int ni = 0; ni < 8; ++ni) {
            int col0 = n0 + wn * 64 + ni * 8 + t4 * 2;
            float b0 = bias[col0], b1 = bias[col0 + 1];
#pragma unroll
            for (int h = 0; h < 2; ++h) {
                int r = m0 + wm * 32 + mi * 16 + h * 8 + g;
                float e0 = (col0 == PAD_IDX)     ? 0.f : __expf(acc[mi][ni][h * 2 + 0] + b0);
                float e1 = (col0 + 1 == PAD_IDX) ? 0.f : __expf(acc[mi][ni][h * 2 + 1] + b1);
                rs[mi][h] += e0 + e1;
                float2 v; v.x = e0; v.y = e1;
                *reinterpret_cast<float2*>(out + (long long)r * OUTC + col0) = v;
            }
        }
    }
#pragma unroll
    for (int mi = 0; mi < 2; ++mi)
#pragma unroll
        for (int h = 0; h < 2; ++h) {
            int rl = wm * 32 + mi * 16 + h * 8 + g;
            atomicAdd(&sRow[rl], rs[mi][h]);
        }
    __syncthreads();
    if (tid < BM) atomicAdd(&g_rowsum[m0 + tid], sRow[tid]);
}

// ============================================================
// Kernel 4: per-row scale = (1 - p_copy) / rowsum
// ============================================================
__global__ void scale_kernel() {
    int i = blockIdx.x * blockDim.x + threadIdx.x;
    if (i < NROWS) g_scale[i] = (1.f - g_pcopy[i]) / g_rowsum[i];
}

// ============================================================
// Kernel 5: in-place normalize of the vocab region (float4 vectorized)
// ============================================================
__global__ void finalize_kernel(float* __restrict__ out) {
    long long idx = (long long)blockIdx.x * blockDim.x + threadIdx.x;  // float4 index
    int row = (int)(idx / (VOCAB / 4));
    int c4  = (int)(idx - (long long)row * (VOCAB / 4));
    if (row >= NROWS) return;
    float s = g_scale[row];
    float4* p = reinterpret_cast<float4*>(out + (long long)row * OUTC) + c4;
    float4 v = *p;
    v.x *= s; v.y *= s; v.z *= s; v.w *= s;
    *p = v;
}

// ============================================================
extern "C" void kernel_launch(void* const* d_in, const int* in_sizes, int n_in,
                              void* d_out, int out_size) {
    const float* hidden  = (const float*)d_in[0];
    const float* attn    = (const float*)d_in[1];
    const float* src_map = (const float*)d_in[2];
    const float* W       = (const float*)d_in[3];
    const float* b       = (const float*)d_in[4];
    const float* W_copy  = (const float*)d_in[5];
    const float* b_copy  = (const float*)d_in[6];
    float* out = (float*)d_out;

    prep_kernel<<<NROWS / 8, 256>>>(hidden, W_copy, b_copy, out, (long long)out_size);
    copy_kernel<<<NROWS, 128>>>(attn, src_map, out);
    dim3 grid(VOCAB / BN, NROWS / BM);   // (250, 16)
    gemm_kernel<<<grid, 256>>>(hidden, W, b, out);
    scale_kernel<<<(NROWS + 255) / 256, 256>>>();
    finalize_kernel<<<(NROWS * (VOCAB / 4)) / 256, 256>>>(out);
}

// round 8
// speedup vs baseline: 2.7476x; 2.7476x over previous
#include <cuda_runtime.h>
#include <cuda_fp16.h>
#include <stdint.h>

#define BATCHN  16
#define NROWS   2048
#define DIM     1024
#define VOCAB   32000
#define CVOCAB  120
#define SLEN    400
#define AGENDA  100
#define CTX     300
#define OUTC    (VOCAB + CVOCAB)   // 32120
#define PAD_IDX 1

// ---- device scratch (static, no allocation) ----
__device__ float g_pcopy[NROWS];
__device__ float g_rowsum[NROWS];
__device__ float g_scale[NROWS];
__device__ __align__(16) __half g_A16[NROWS * DIM];            // 4 MB
__device__ __align__(16) __half g_B16[(size_t)VOCAB * DIM];    // 64 MB

// ============================================================
// fp32 -> fp16 conversion kernels (W split in two for launch ordering)
// ============================================================
__global__ void convW_kernel(const float* __restrict__ W, int rowOff) {
    long long i = (long long)blockIdx.x * blockDim.x + threadIdx.x;   // float4 index
    long long n4 = (long long)16000 * DIM / 4;
    if (i >= n4) return;
    long long base = (long long)rowOff * DIM / 4;
    float4 v = reinterpret_cast<const float4*>(W)[base + i];
    __half2 h0 = __floats2half2_rn(v.x, v.y);
    __half2 h1 = __floats2half2_rn(v.z, v.w);
    uint2 u; u.x = *reinterpret_cast<uint32_t*>(&h0); u.y = *reinterpret_cast<uint32_t*>(&h1);
    reinterpret_cast<uint2*>(g_B16)[base + i] = u;
}

__global__ void convH_kernel(const float* __restrict__ hidden) {
    long long i = (long long)blockIdx.x * blockDim.x + threadIdx.x;
    if (i >= (long long)NROWS * DIM / 4) return;
    float4 v = reinterpret_cast<const float4*>(hidden)[i];
    __half2 h0 = __floats2half2_rn(v.x, v.y);
    __half2 h1 = __floats2half2_rn(v.z, v.w);
    uint2 u; u.x = *reinterpret_cast<uint32_t*>(&h0); u.y = *reinterpret_cast<uint32_t*>(&h1);
    reinterpret_cast<uint2*>(g_A16)[i] = u;
}

// ============================================================
// prep: p_copy = sigmoid(hidden @ Wc^T + bc); zero rowsum; p_copy tail
// ============================================================
__global__ void prep_kernel(const float* __restrict__ hidden,
                            const float* __restrict__ Wc,
                            const float* __restrict__ bc,
                            float* __restrict__ out, long long out_size) {
    int warp = (blockIdx.x * blockDim.x + threadIdx.x) >> 5;
    int lane = threadIdx.x & 31;
    if (warp >= NROWS) return;
    const float* h = hidden + (long long)warp * DIM;
    float s = 0.f;
#pragma unroll
    for (int j = 0; j < DIM / 32; ++j)
        s += h[j * 32 + lane] * Wc[j * 32 + lane];
#pragma unroll
    for (int o = 16; o > 0; o >>= 1)
        s += __shfl_down_sync(0xffffffffu, s, o);
    if (lane == 0) {
        float p = 1.f / (1.f + __expf(-(s + bc[0])));
        g_pcopy[warp]  = p;
        g_rowsum[warp] = 0.f;
        long long base = (long long)NROWS * OUTC;
        if (out_size >= base + NROWS) out[base + warp] = p;
    }
}

// ============================================================
// copy_prob
// ============================================================
__global__ void copy_kernel(const float* __restrict__ attn,
                            const float* __restrict__ src_map,
                            float* __restrict__ out) {
    int row = blockIdx.x;
    int b   = row & (BATCHN - 1);
    __shared__ float ma[AGENDA];
    float p = g_pcopy[row];
    int t = threadIdx.x;
    if (t < AGENDA) ma[t] = attn[(long long)row * SLEN + CTX + t] * p;
    __syncthreads();
    if (t < CVOCAB) {
        float s = 0.f;
        const float* sm = src_map + b * CVOCAB + t;
#pragma unroll 4
        for (int a = 0; a < AGENDA; ++a)
            s += ma[a] * sm[a * (BATCHN * CVOCAB)];
        out[(long long)row * OUTC + VOCAB + t] = s;
    }
}

// ============================================================
// GEMM: e = exp(hidden @ W^T + b)  (fp16 MMA, cp.async 3-stage, ldmatrix)
// ============================================================
#define BM 128
#define BN 128
#define BK 64
#define STAGE_B 32768           // bytes per stage (A 16KB + B 16KB)
#define SMEM_BYTES 98304        // 3 stages; epilogue tile (67.6KB) reuses this

__device__ __forceinline__ void cp16(uint32_t s, const void* g) {
    asm volatile("cp.async.cg.shared.global [%0], [%1], 16;" :: "r"(s), "l"(g));
}
__device__ __forceinline__ void cp_commit() { asm volatile("cp.async.commit_group;"); }
template<int N> __device__ __forceinline__ void cp_wait() {
    asm volatile("cp.async.wait_group %0;" :: "n"(N));
}
__device__ __forceinline__ void ldsm4(uint32_t& r0, uint32_t& r1, uint32_t& r2, uint32_t& r3, uint32_t a) {
    asm volatile("ldmatrix.sync.aligned.m8n8.x4.shared.b16 {%0,%1,%2,%3},[%4];"
                 : "=r"(r0), "=r"(r1), "=r"(r2), "=r"(r3) : "r"(a));
}
__device__ __forceinline__ void mma16816(float* d, uint32_t a0, uint32_t a1, uint32_t a2, uint32_t a3,
                                         uint32_t b0, uint32_t b1) {
    asm volatile("mma.sync.aligned.m16n8k16.row.col.f32.f16.f16.f32 "
                 "{%0,%1,%2,%3},{%4,%5,%6,%7},{%8,%9},{%0,%1,%2,%3};"
                 : "+f"(d[0]), "+f"(d[1]), "+f"(d[2]), "+f"(d[3])
                 : "r"(a0), "r"(a1), "r"(a2), "r"(a3), "r"(b0), "r"(b1));
}

extern __shared__ char dyn_smem[];

__global__ __launch_bounds__(256, 1)
void gemm_kernel(const float* __restrict__ bias, float* __restrict__ out) {
    const int tid  = threadIdx.x;
    const int lane = tid & 31, warp = tid >> 5;
    const int wm = warp >> 2;        // 0..1 : 64 rows each
    const int wn = warp & 3;         // 0..3 : 32 cols each
    const int m0 = blockIdx.x * BM;  // grid.x = 16 (m fastest -> W tile reused in L2)
    const int n0 = blockIdx.y * BN;  // grid.y = 250

    uint32_t sbase = (uint32_t)__cvta_generic_to_shared(dyn_smem);

    // global->shared load mapping
    const int lr = tid >> 3, c = tid & 7;
    const int swc = c ^ (lr & 7);
    const __half* gA = g_A16 + (size_t)(m0 + lr) * DIM + c * 8;
    const __half* gB = g_B16 + (size_t)(n0 + lr) * DIM + c * 8;
    const uint32_t sA0 = sbase + lr * 128 + swc * 16;
    const uint32_t sB0 = sbase + 16384 + lr * 128 + swc * 16;

    float acc[4][4][4];
#pragma unroll
    for (int mi = 0; mi < 4; ++mi)
#pragma unroll
        for (int nf = 0; nf < 4; ++nf)
#pragma unroll
            for (int x = 0; x < 4; ++x) acc[mi][nf][x] = 0.f;

    // fragment-load lane geometry
    const int lrow = lane & 15;       // row within 16-row tile
    const int lk   = lane >> 4;       // 0/1 (8-col chunk)
    const int lsw  = lane & 7;        // swizzle key (== row&7, tile bases mult of 16)

    // prologue: stages 0,1
#pragma unroll
    for (int i = 0; i < 4; ++i) {
        cp16(sA0 + i * 32 * 128, gA + i * 32 * DIM);
        cp16(sB0 + i * 32 * 128, gB + i * 32 * DIM);
    }
    cp_commit();
#pragma unroll
    for (int i = 0; i < 4; ++i) {
        cp16(sA0 + STAGE_B + i * 32 * 128, gA + 64 + i * 32 * DIM);
        cp16(sB0 + STAGE_B + i * 32 * 128, gB + 64 + i * 32 * DIM);
    }
    cp_commit();

    for (int kc = 0; kc < DIM / BK; ++kc) {
        cp_wait<1>();
        __syncthreads();
        if (kc + 2 < DIM / BK) {
            int s2 = (kc + 2) % 3;
#pragma unroll
            for (int i = 0; i < 4; ++i) {
                cp16(sA0 + s2 * STAGE_B + i * 32 * 128, gA + (kc + 2) * 64 + i * 32 * DIM);
                cp16(sB0 + s2 * STAGE_B + i * 32 * 128, gB + (kc + 2) * 64 + i * 32 * DIM);
            }
        }
        cp_commit();

        const int s = kc % 3;
        const uint32_t abase = sbase + s * STAGE_B;
        const uint32_t bbase = abase + 16384;
#pragma unroll
        for (int kk = 0; kk < 4; ++kk) {
            uint32_t a[4][4];
            uint32_t bfr[4][2];
#pragma unroll
            for (int mi = 0; mi < 4; ++mi) {
                int r = wm * 64 + mi * 16 + lrow;
                uint32_t addr = abase + r * 128 + (((kk * 2 + lk) ^ lsw) * 16);
                ldsm4(a[mi][0], a[mi][1], a[mi][2], a[mi][3], addr);
            }
#pragma unroll
            for (int nj = 0; nj < 2; ++nj) {
                int r = wn * 32 + nj * 16 + lrow;
                uint32_t addr = bbase + r * 128 + (((kk * 2 + lk) ^ lsw) * 16);
                uint32_t t0, t1, t2, t3;
                ldsm4(t0, t1, t2, t3, addr);
                bfr[nj * 2][0] = t0;     bfr[nj * 2][1] = t2;
                bfr[nj * 2 + 1][0] = t1; bfr[nj * 2 + 1][1] = t3;
            }
#pragma unroll
            for (int mi = 0; mi < 4; ++mi)
#pragma unroll
                for (int nf = 0; nf < 4; ++nf)
                    mma16816(acc[mi][nf], a[mi][0], a[mi][1], a[mi][2], a[mi][3],
                             bfr[nf][0], bfr[nf][1]);
        }
        __syncthreads();
    }

    // ---- epilogue: stage tile in smem, then coalesced exp+bias+store+rowsum ----
    float* sOut = reinterpret_cast<float*>(dyn_smem);
    const int OS = 132;   // floats; stride 528B = 16B-aligned for float4 reads
#pragma unroll
    for (int mi = 0; mi < 4; ++mi)
#pragma unroll
        for (int nf = 0; nf < 4; ++nf) {
            int m = wm * 64 + mi * 16 + (lane >> 2);
            int n = wn * 32 + nf * 8 + (lane & 3) * 2;
            sOut[m * OS + n]           = acc[mi][nf][0];
            sOut[m * OS + n + 1]       = acc[mi][nf][1];
            sOut[(m + 8) * OS + n]     = acc[mi][nf][2];
            sOut[(m + 8) * OS + n + 1] = acc[mi][nf][3];
        }
    __syncthreads();

    // warp w handles rows w*16..w*16+15; lane -> float4 column lane
    const int cb = n0 + lane * 4;
    const float4 bv = *reinterpret_cast<const float4*>(bias + cb);
#pragma unroll
    for (int rr = 0; rr < 16; ++rr) {
        int row = warp * 16 + rr;
        float4 v = *reinterpret_cast<float4*>(sOut + row * OS + lane * 4);
        v.x = __expf(v.x + bv.x);
        v.y = __expf(v.y + bv.y);
        v.z = __expf(v.z + bv.z);
        v.w = __expf(v.w + bv.w);
        if (n0 == 0 && lane == 0) v.y = 0.f;   // PAD_IDX == 1
        float rsum = v.x + v.y + v.z + v.w;
#pragma unroll
        for (int o = 16; o > 0; o >>= 1)
            rsum += __shfl_xor_sync(0xffffffffu, rsum, o);
        *reinterpret_cast<float4*>(out + (size_t)(m0 + row) * OUTC + cb) = v;
        if (lane == 0) atomicAdd(&g_rowsum[m0 + row], rsum);
    }
}

// ============================================================
// scale + finalize
// ============================================================
__global__ void scale_kernel() {
    int i = blockIdx.x * blockDim.x + threadIdx.x;
    if (i < NROWS) g_scale[i] = (1.f - g_pcopy[i]) / g_rowsum[i];
}

__global__ void finalize_kernel(float* __restrict__ out) {
    long long idx = (long long)blockIdx.x * blockDim.x + threadIdx.x;  // float4 index
    int row = (int)(idx / (VOCAB / 4));
    int c4  = (int)(idx - (long long)row * (VOCAB / 4));
    if (row >= NROWS) return;
    float s = g_scale[row];
    float4* p = reinterpret_cast<float4*>(out + (long long)row * OUTC) + c4;
    float4 v = *p;
    v.x *= s; v.y *= s; v.z *= s; v.w *= s;
    *p = v;
}

// ============================================================
extern "C" void kernel_launch(void* const* d_in, const int* in_sizes, int n_in,
                              void* d_out, int out_size) {
    const float* hidden  = (const float*)d_in[0];
    const float* attn    = (const float*)d_in[1];
    const float* src_map = (const float*)d_in[2];
    const float* W       = (const float*)d_in[3];
    const float* b       = (const float*)d_in[4];
    const float* W_copy  = (const float*)d_in[5];
    const float* b_copy  = (const float*)d_in[6];
    float* out = (float*)d_out;

    cudaFuncSetAttribute(gemm_kernel, cudaFuncAttributeMaxDynamicSharedMemorySize, SMEM_BYTES);

    // launch order chosen so gemm_kernel is launch index 5 (ncu -s 5 -c 1)
    convW_kernel<<<16000, 256>>>(W, 0);                    // 0
    convW_kernel<<<16000, 256>>>(W, 16000);                // 1
    convH_kernel<<<2048, 256>>>(hidden);                   // 2
    prep_kernel<<<NROWS / 8, 256>>>(hidden, W_copy, b_copy, out, (long long)out_size);  // 3
    copy_kernel<<<NROWS, 128>>>(attn, src_map, out);       // 4
    dim3 grid(NROWS / BM, VOCAB / BN);                     // (16, 250), m fastest
    gemm_kernel<<<grid, 256, SMEM_BYTES>>>(b, out);        // 5
    scale_kernel<<<(NROWS + 255) / 256, 256>>>();          // 6
    finalize_kernel<<<(NROWS * (VOCAB / 4)) / 256, 256>>>(out);  // 7
}

// round 10
// speedup vs baseline: 2.7590x; 1.0042x over previous
#include <cuda_runtime.h>
#include <cuda_fp16.h>
#include <stdint.h>

#define BATCHN  16
#define NROWS   2048
#define DIM     1024
#define VOCAB   32000
#define CVOCAB  120
#define SLEN    400
#define AGENDA  100
#define CTX     300
#define OUTC    (VOCAB + CVOCAB)   // 32120
#define PAD_IDX 1

// ---- device scratch (static, no allocation) ----
__device__ float g_pcopy[NROWS];
__device__ float g_rowsum[NROWS];
__device__ __align__(16) __half g_A16[NROWS * DIM];            // 4 MB
__device__ __align__(16) __half g_B16[(size_t)VOCAB * DIM];    // 64 MB

// ============================================================
// fp32 -> fp16 conversion kernels
// ============================================================
__global__ void convW_kernel(const float* __restrict__ W) {
    long long i = (long long)blockIdx.x * blockDim.x + threadIdx.x;   // float4 index
    if (i >= (long long)VOCAB * DIM / 4) return;
    float4 v = reinterpret_cast<const float4*>(W)[i];
    __half2 h0 = __floats2half2_rn(v.x, v.y);
    __half2 h1 = __floats2half2_rn(v.z, v.w);
    uint2 u; u.x = *reinterpret_cast<uint32_t*>(&h0); u.y = *reinterpret_cast<uint32_t*>(&h1);
    reinterpret_cast<uint2*>(g_B16)[i] = u;
}
__global__ void convH_kernel(const float* __restrict__ hidden) {
    long long i = (long long)blockIdx.x * blockDim.x + threadIdx.x;
    if (i >= (long long)NROWS * DIM / 4) return;
    float4 v = reinterpret_cast<const float4*>(hidden)[i];
    __half2 h0 = __floats2half2_rn(v.x, v.y);
    __half2 h1 = __floats2half2_rn(v.z, v.w);
    uint2 u; u.x = *reinterpret_cast<uint32_t*>(&h0); u.y = *reinterpret_cast<uint32_t*>(&h1);
    reinterpret_cast<uint2*>(g_A16)[i] = u;
}

// ============================================================
// prep: p_copy = sigmoid(hidden @ Wc^T + bc); zero rowsum; p_copy tail
// ============================================================
__global__ void prep_kernel(const float* __restrict__ hidden,
                            const float* __restrict__ Wc,
                            const float* __restrict__ bc,
                            float* __restrict__ out, long long out_size) {
    int warp = (blockIdx.x * blockDim.x + threadIdx.x) >> 5;
    int lane = threadIdx.x & 31;
    if (warp >= NROWS) return;
    const float* h = hidden + (long long)warp * DIM;
    float s = 0.f;
#pragma unroll
    for (int j = 0; j < DIM / 32; ++j)
        s += h[j * 32 + lane] * Wc[j * 32 + lane];
#pragma unroll
    for (int o = 16; o > 0; o >>= 1)
        s += __shfl_down_sync(0xffffffffu, s, o);
    if (lane == 0) {
        float p = 1.f / (1.f + __expf(-(s + bc[0])));
        g_pcopy[warp]  = p;
        g_rowsum[warp] = 0.f;
        long long base = (long long)NROWS * OUTC;
        if (out_size >= base + NROWS) out[base + warp] = p;
    }
}

// ============================================================
// copy_prob
// ============================================================
__global__ void copy_kernel(const float* __restrict__ attn,
                            const float* __restrict__ src_map,
                            float* __restrict__ out) {
    int row = blockIdx.x;
    int b   = row & (BATCHN - 1);
    __shared__ float ma[AGENDA];
    float p = g_pcopy[row];
    int t = threadIdx.x;
    if (t < AGENDA) ma[t] = attn[(long long)row * SLEN + CTX + t] * p;
    __syncthreads();
    if (t < CVOCAB) {
        float s = 0.f;
        const float* sm = src_map + b * CVOCAB + t;
#pragma unroll 4
        for (int a = 0; a < AGENDA; ++a)
            s += ma[a] * sm[a * (BATCHN * CVOCAB)];
        out[(long long)row * OUTC + VOCAB + t] = s;
    }
}

// ============================================================
// GEMM: e = exp(hidden @ W^T + b)  (fp16 mma.sync, 2-stage cp.async, occ=2)
// ============================================================
#define BM 128
#define BN 128
#define BK 64
#define STAGE_B 32768           // bytes per stage (A 16KB + B 16KB)
#define SMEM_BYTES 65536        // 2 stages; epilogue half-tile (33.8KB) reuses this

__device__ __forceinline__ void cp16(uint32_t s, const void* g) {
    asm volatile("cp.async.cg.shared.global [%0], [%1], 16;" :: "r"(s), "l"(g));
}
__device__ __forceinline__ void cp_commit() { asm volatile("cp.async.commit_group;"); }
template<int N> __device__ __forceinline__ void cp_wait() {
    asm volatile("cp.async.wait_group %0;" :: "n"(N));
}
__device__ __forceinline__ void ldsm4(uint32_t& r0, uint32_t& r1, uint32_t& r2, uint32_t& r3, uint32_t a) {
    asm volatile("ldmatrix.sync.aligned.m8n8.x4.shared.b16 {%0,%1,%2,%3},[%4];"
                 : "=r"(r0), "=r"(r1), "=r"(r2), "=r"(r3) : "r"(a));
}
__device__ __forceinline__ void mma16816(float* d, uint32_t a0, uint32_t a1, uint32_t a2, uint32_t a3,
                                         uint32_t b0, uint32_t b1) {
    asm volatile("mma.sync.aligned.m16n8k16.row.col.f32.f16.f16.f32 "
                 "{%0,%1,%2,%3},{%4,%5,%6,%7},{%8,%9},{%0,%1,%2,%3};"
                 : "+f"(d[0]), "+f"(d[1]), "+f"(d[2]), "+f"(d[3])
                 : "r"(a0), "r"(a1), "r"(a2), "r"(a3), "r"(b0), "r"(b1));
}

extern __shared__ char dyn_smem[];

__global__ __launch_bounds__(256, 2)
void gemm_kernel(const float* __restrict__ bias, float* __restrict__ out) {
    const int tid  = threadIdx.x;
    const int lane = tid & 31, warp = tid >> 5;
    const int wm = warp >> 2;        // 0..1 : 64 rows each
    const int wn = warp & 3;         // 0..3 : 32 cols each
    const int m0 = blockIdx.x * BM;  // grid.x = 16 (m fastest -> W tile reused in L2)
    const int n0 = blockIdx.y * BN;  // grid.y = 250

    uint32_t sbase = (uint32_t)__cvta_generic_to_shared(dyn_smem);

    // global->shared load mapping
    const int lr = tid >> 3, c = tid & 7;
    const int swc = c ^ (lr & 7);
    const __half* gA = g_A16 + (size_t)(m0 + lr) * DIM + c * 8;
    const __half* gB = g_B16 + (size_t)(n0 + lr) * DIM + c * 8;
    const uint32_t sA0 = sbase + lr * 128 + swc * 16;
    const uint32_t sB0 = sbase + 16384 + lr * 128 + swc * 16;

    float acc[4][4][4];
#pragma unroll
    for (int mi = 0; mi < 4; ++mi)
#pragma unroll
        for (int nf = 0; nf < 4; ++nf)
#pragma unroll
            for (int x = 0; x < 4; ++x) acc[mi][nf][x] = 0.f;

    // fragment-load lane geometry
    const int lrow = lane & 15;       // row within 16-row tile
    const int lk   = lane >> 4;       // 0/1 (8-col chunk)
    const int lsw  = lane & 7;        // swizzle key (== row&7, tile bases mult of 16)

    // prologue: stage 0
#pragma unroll
    for (int i = 0; i < 4; ++i) {
        cp16(sA0 + i * 32 * 128, gA + i * 32 * DIM);
        cp16(sB0 + i * 32 * 128, gB + i * 32 * DIM);
    }
    cp_commit();

    for (int kc = 0; kc < DIM / BK; ++kc) {
        // prefetch next stage (other buffer), commit unconditionally
        if (kc + 1 < DIM / BK) {
            const uint32_t so = ((kc + 1) & 1) * STAGE_B;
#pragma unroll
            for (int i = 0; i < 4; ++i) {
                cp16(sA0 + so + i * 32 * 128, gA + (kc + 1) * 64 + i * 32 * DIM);
                cp16(sB0 + so + i * 32 * 128, gB + (kc + 1) * 64 + i * 32 * DIM);
            }
        }
        cp_commit();
        cp_wait<1>();        // current stage's group complete
        __syncthreads();

        const uint32_t abase = sbase + (kc & 1) * STAGE_B;
        const uint32_t bbase = abase + 16384;
#pragma unroll
        for (int kk = 0; kk < 4; ++kk) {
            uint32_t a[4][4];
            uint32_t bfr[4][2];
#pragma unroll
            for (int mi = 0; mi < 4; ++mi) {
                int r = wm * 64 + mi * 16 + lrow;
                uint32_t addr = abase + r * 128 + (((kk * 2 + lk) ^ lsw) * 16);
                ldsm4(a[mi][0], a[mi][1], a[mi][2], a[mi][3], addr);
            }
#pragma unroll
            for (int nj = 0; nj < 2; ++nj) {
                int r = wn * 32 + nj * 16 + lrow;
                uint32_t addr = bbase + r * 128 + (((kk * 2 + lk) ^ lsw) * 16);
                uint32_t t0, t1, t2, t3;
                ldsm4(t0, t1, t2, t3, addr);
                bfr[nj * 2][0] = t0;     bfr[nj * 2][1] = t2;
                bfr[nj * 2 + 1][0] = t1; bfr[nj * 2 + 1][1] = t3;
            }
#pragma unroll
            for (int mi = 0; mi < 4; ++mi)
#pragma unroll
                for (int nf = 0; nf < 4; ++nf)
                    mma16816(acc[mi][nf], a[mi][0], a[mi][1], a[mi][2], a[mi][3],
                             bfr[nf][0], bfr[nf][1]);
        }
        __syncthreads();
    }

    // ---- epilogue in two 64-row halves (fits 64KB smem) ----
    float* sOut = reinterpret_cast<float*>(dyn_smem);
    const int OS = 132;   // floats; stride 528B, 16B-aligned
    const int cb = n0 + lane * 4;
    const float4 bv = *reinterpret_cast<const float4*>(bias + cb);

#pragma unroll
    for (int h = 0; h < 2; ++h) {
        if (wm == h) {
#pragma unroll
            for (int mi = 0; mi < 4; ++mi)
#pragma unroll
                for (int nf = 0; nf < 4; ++nf) {
                    int m = mi * 16 + (lane >> 2);          // local row in half
                    int n = wn * 32 + nf * 8 + (lane & 3) * 2;
                    sOut[m * OS + n]           = acc[mi][nf][0];
                    sOut[m * OS + n + 1]       = acc[mi][nf][1];
                    sOut[(m + 8) * OS + n]     = acc[mi][nf][2];
                    sOut[(m + 8) * OS + n + 1] = acc[mi][nf][3];
                }
        }
        __syncthreads();

        // warp w handles rows w*8 .. w*8+7 of this half
#pragma unroll
        for (int rr = 0; rr < 8; ++rr) {
            int rl = warp * 8 + rr;
            float4 v = *reinterpret_cast<float4*>(sOut + rl * OS + lane * 4);
            v.x = __expf(v.x + bv.x);
            v.y = __expf(v.y + bv.y);
            v.z = __expf(v.z + bv.z);
            v.w = __expf(v.w + bv.w);
            if (n0 == 0 && lane == 0) v.y = 0.f;   // PAD_IDX == 1
            float rsum = v.x + v.y + v.z + v.w;
#pragma unroll
            for (int o = 16; o > 0; o >>= 1)
                rsum += __shfl_xor_sync(0xffffffffu, rsum, o);
            int grow = m0 + h * 64 + rl;
            *reinterpret_cast<float4*>(out + (size_t)grow * OUTC + cb) = v;
            if (lane == 0) atomicAdd(&g_rowsum[grow], rsum);
        }
        __syncthreads();
    }
}

// ============================================================
// finalize: out[row, 0:VOCAB] *= (1 - p_copy)/rowsum
// ============================================================
__global__ void finalize_kernel(float* __restrict__ out) {
    long long idx = (long long)blockIdx.x * blockDim.x + threadIdx.x;  // float4 index
    int row = (int)(idx / (VOCAB / 4));
    int c4  = (int)(idx - (long long)row * (VOCAB / 4));
    if (row >= NROWS) return;
    float s = (1.f - g_pcopy[row]) * __frcp_rn(g_rowsum[row]);
    float4* p = reinterpret_cast<float4*>(out + (long long)row * OUTC) + c4;
    float4 v = *p;
    v.x *= s; v.y *= s; v.z *= s; v.w *= s;
    *p = v;
}

// ============================================================
extern "C" void kernel_launch(void* const* d_in, const int* in_sizes, int n_in,
                              void* d_out, int out_size) {
    const float* hidden  = (const float*)d_in[0];
    const float* attn    = (const float*)d_in[1];
    const float* src_map = (const float*)d_in[2];
    const float* W       = (const float*)d_in[3];
    const float* b       = (const float*)d_in[4];
    const float* W_copy  = (const float*)d_in[5];
    const float* b_copy  = (const float*)d_in[6];
    float* out = (float*)d_out;

    cudaFuncSetAttribute(gemm_kernel, cudaFuncAttributeMaxDynamicSharedMemorySize, SMEM_BYTES);

    convW_kernel<<<32000, 256>>>(W);                                         // 0
    convH_kernel<<<2048, 256>>>(hidden);                                     // 1
    prep_kernel<<<NROWS / 8, 256>>>(hidden, W_copy, b_copy, out, (long long)out_size); // 2
    dim3 grid(NROWS / BM, VOCAB / BN);                                       // (16, 250)
    gemm_kernel<<<grid, 256, SMEM_BYTES>>>(b, out);                          // 3 (profiled)
    copy_kernel<<<NROWS, 128>>>(attn, src_map, out);                         // 4
    finalize_kernel<<<(NROWS * (VOCAB / 4)) / 256, 256>>>(out);              // 5
}

// round 11
// speedup vs baseline: 2.8610x; 1.0370x over previous
#include <cuda_runtime.h>
#include <cuda_fp16.h>
#include <stdint.h>

#define BATCHN  16
#define NROWS   2048
#define DIM     1024
#define VOCAB   32000
#define CVOCAB  120
#define SLEN    400
#define AGENDA  100
#define CTX     300
#define OUTC    (VOCAB + CVOCAB)   // 32120
#define PAD_IDX 1

// ---- device scratch (static, no allocation) ----
__device__ float g_pcopy[NROWS];
__device__ float g_rowsum[NROWS];
__device__ __align__(16) __half g_A16[NROWS * DIM];            // 4 MB
__device__ __align__(16) __half g_B16[(size_t)VOCAB * DIM];    // 64 MB
__device__ __align__(16) __half g_E16[(size_t)NROWS * VOCAB];  // 131 MB (e = exp(logit+b))

// ============================================================
// fp32 -> fp16 conversion kernels
// ============================================================
__global__ void convW_kernel(const float* __restrict__ W) {
    long long i = (long long)blockIdx.x * blockDim.x + threadIdx.x;   // float4 index
    if (i >= (long long)VOCAB * DIM / 4) return;
    float4 v = reinterpret_cast<const float4*>(W)[i];
    __half2 h0 = __floats2half2_rn(v.x, v.y);
    __half2 h1 = __floats2half2_rn(v.z, v.w);
    uint2 u; u.x = *reinterpret_cast<uint32_t*>(&h0); u.y = *reinterpret_cast<uint32_t*>(&h1);
    reinterpret_cast<uint2*>(g_B16)[i] = u;
}
__global__ void convH_kernel(const float* __restrict__ hidden) {
    long long i = (long long)blockIdx.x * blockDim.x + threadIdx.x;
    if (i >= (long long)NROWS * DIM / 4) return;
    float4 v = reinterpret_cast<const float4*>(hidden)[i];
    __half2 h0 = __floats2half2_rn(v.x, v.y);
    __half2 h1 = __floats2half2_rn(v.z, v.w);
    uint2 u; u.x = *reinterpret_cast<uint32_t*>(&h0); u.y = *reinterpret_cast<uint32_t*>(&h1);
    reinterpret_cast<uint2*>(g_A16)[i] = u;
}

// ============================================================
// prep: p_copy = sigmoid(hidden @ Wc^T + bc); zero rowsum; p_copy tail
// ============================================================
__global__ void prep_kernel(const float* __restrict__ hidden,
                            const float* __restrict__ Wc,
                            const float* __restrict__ bc,
                            float* __restrict__ out, long long out_size) {
    int warp = (blockIdx.x * blockDim.x + threadIdx.x) >> 5;
    int lane = threadIdx.x & 31;
    if (warp >= NROWS) return;
    const float* h = hidden + (long long)warp * DIM;
    float s = 0.f;
#pragma unroll
    for (int j = 0; j < DIM / 32; ++j)
        s += h[j * 32 + lane] * Wc[j * 32 + lane];
#pragma unroll
    for (int o = 16; o > 0; o >>= 1)
        s += __shfl_down_sync(0xffffffffu, s, o);
    if (lane == 0) {
        float p = 1.f / (1.f + __expf(-(s + bc[0])));
        g_pcopy[warp]  = p;
        g_rowsum[warp] = 0.f;
        long long base = (long long)NROWS * OUTC;
        if (out_size >= base + NROWS) out[base + warp] = p;
    }
}

// ============================================================
// copy_prob
// ============================================================
__global__ void copy_kernel(const float* __restrict__ attn,
                            const float* __restrict__ src_map,
                            float* __restrict__ out) {
    int row = blockIdx.x;
    int b   = row & (BATCHN - 1);
    __shared__ float ma[AGENDA];
    float p = g_pcopy[row];
    int t = threadIdx.x;
    if (t < AGENDA) ma[t] = attn[(long long)row * SLEN + CTX + t] * p;
    __syncthreads();
    if (t < CVOCAB) {
        float s = 0.f;
        const float* sm = src_map + b * CVOCAB + t;
#pragma unroll 4
        for (int a = 0; a < AGENDA; ++a)
            s += ma[a] * sm[a * (BATCHN * CVOCAB)];
        out[(long long)row * OUTC + VOCAB + t] = s;
    }
}

// ============================================================
// GEMM: e = exp(hidden @ W^T + b) -> g_E16 (half), rowsum atomics
//   fp16 mma.sync, 3-stage cp.async, occ=2, hoisted LDSM addresses
// ============================================================
#define BM 128
#define BN 128
#define BK 64
#define STAGE_B 32768           // A 16KB + B 16KB per stage
#define SMEM_BYTES 98304        // 3 stages; epilogue tile (67.6KB) reuses this

__device__ __forceinline__ void cp16(uint32_t s, const void* g) {
    asm volatile("cp.async.cg.shared.global [%0], [%1], 16;" :: "r"(s), "l"(g));
}
__device__ __forceinline__ void cp_commit() { asm volatile("cp.async.commit_group;"); }
template<int N> __device__ __forceinline__ void cp_wait() {
    asm volatile("cp.async.wait_group %0;" :: "n"(N));
}
__device__ __forceinline__ void ldsm4(uint32_t& r0, uint32_t& r1, uint32_t& r2, uint32_t& r3, uint32_t a) {
    asm volatile("ldmatrix.sync.aligned.m8n8.x4.shared.b16 {%0,%1,%2,%3},[%4];"
                 : "=r"(r0), "=r"(r1), "=r"(r2), "=r"(r3) : "r"(a));
}
__device__ __forceinline__ void mma16816(float* d, uint32_t a0, uint32_t a1, uint32_t a2, uint32_t a3,
                                         uint32_t b0, uint32_t b1) {
    asm volatile("mma.sync.aligned.m16n8k16.row.col.f32.f16.f16.f32 "
                 "{%0,%1,%2,%3},{%4,%5,%6,%7},{%8,%9},{%0,%1,%2,%3};"
                 : "+f"(d[0]), "+f"(d[1]), "+f"(d[2]), "+f"(d[3])
                 : "r"(a0), "r"(a1), "r"(a2), "r"(a3), "r"(b0), "r"(b1));
}

extern __shared__ char dyn_smem[];

__global__ __launch_bounds__(256, 2)
void gemm_kernel(const float* __restrict__ bias) {
    const int tid  = threadIdx.x;
    const int lane = tid & 31, warp = tid >> 5;
    const int wm = warp >> 2;        // 0..1 : 64 rows each
    const int wn = warp & 3;         // 0..3 : 32 cols each
    const int m0 = blockIdx.x * BM;  // grid.x = 16 (m fastest -> W tile reused in L2)
    const int n0 = blockIdx.y * BN;  // grid.y = 250

    uint32_t sbase = (uint32_t)__cvta_generic_to_shared(dyn_smem);

    // global->shared load mapping
    const int lr = tid >> 3, c = tid & 7;
    const int swc = c ^ (lr & 7);
    const __half* gA = g_A16 + (size_t)(m0 + lr) * DIM + c * 8;
    const __half* gB = g_B16 + (size_t)(n0 + lr) * DIM + c * 8;
    const uint32_t sA0 = sbase + lr * 128 + swc * 16;
    const uint32_t sB0 = sbase + 16384 + lr * 128 + swc * 16;

    float acc[4][4][4];
#pragma unroll
    for (int mi = 0; mi < 4; ++mi)
#pragma unroll
        for (int nf = 0; nf < 4; ++nf)
#pragma unroll
            for (int x = 0; x < 4; ++x) acc[mi][nf][x] = 0.f;

    // ---- hoisted fragment-load addresses (stage-0 based) ----
    const int lrow = lane & 15;
    const int lk   = lane >> 4;
    const int lsw  = lane & 7;
    uint32_t rA[4], rB[2], xk[4];
#pragma unroll
    for (int mi = 0; mi < 4; ++mi)
        rA[mi] = sbase + (wm * 64 + mi * 16 + lrow) * 128;
#pragma unroll
    for (int nj = 0; nj < 2; ++nj)
        rB[nj] = sbase + 16384 + (wn * 32 + nj * 16 + lrow) * 128;
#pragma unroll
    for (int kk = 0; kk < 4; ++kk)
        xk[kk] = (uint32_t)(((kk * 2 + lk) ^ lsw) * 16);

    // prologue: stages 0,1
#pragma unroll
    for (int i = 0; i < 4; ++i) {
        cp16(sA0 + i * 32 * 128, gA + i * 32 * DIM);
        cp16(sB0 + i * 32 * 128, gB + i * 32 * DIM);
    }
    cp_commit();
#pragma unroll
    for (int i = 0; i < 4; ++i) {
        cp16(sA0 + STAGE_B + i * 32 * 128, gA + 64 + i * 32 * DIM);
        cp16(sB0 + STAGE_B + i * 32 * 128, gB + 64 + i * 32 * DIM);
    }
    cp_commit();

    for (int kc = 0; kc < DIM / BK; ++kc) {
        cp_wait<1>();
        __syncthreads();
        if (kc + 2 < DIM / BK) {
            const uint32_t so = ((kc + 2) % 3) * STAGE_B;
#pragma unroll
            for (int i = 0; i < 4; ++i) {
                cp16(sA0 + so + i * 32 * 128, gA + (kc + 2) * 64 + i * 32 * DIM);
                cp16(sB0 + so + i * 32 * 128, gB + (kc + 2) * 64 + i * 32 * DIM);
            }
        }
        cp_commit();

        const uint32_t soff = (kc % 3) * STAGE_B;
#pragma unroll
        for (int kk = 0; kk < 4; ++kk) {
            const uint32_t xo = xk[kk] + soff;
            uint32_t a[4][4];
            uint32_t bfr[4][2];
#pragma unroll
            for (int mi = 0; mi < 4; ++mi)
                ldsm4(a[mi][0], a[mi][1], a[mi][2], a[mi][3], rA[mi] + xo);
#pragma unroll
            for (int nj = 0; nj < 2; ++nj) {
                uint32_t t0, t1, t2, t3;
                ldsm4(t0, t1, t2, t3, rB[nj] + xo);
                bfr[nj * 2][0] = t0;     bfr[nj * 2][1] = t2;
                bfr[nj * 2 + 1][0] = t1; bfr[nj * 2 + 1][1] = t3;
            }
#pragma unroll
            for (int mi = 0; mi < 4; ++mi)
#pragma unroll
                for (int nf = 0; nf < 4; ++nf)
                    mma16816(acc[mi][nf], a[mi][0], a[mi][1], a[mi][2], a[mi][3],
                             bfr[nf][0], bfr[nf][1]);
        }
        __syncthreads();
    }

    // ---- epilogue: stage full tile in smem, exp+bias, half store, rowsum ----
    float* sOut = reinterpret_cast<float*>(dyn_smem);
    const int OS = 132;   // floats; stride 528B, 16B-aligned
#pragma unroll
    for (int mi = 0; mi < 4; ++mi)
#pragma unroll
        for (int nf = 0; nf < 4; ++nf) {
            int m = wm * 64 + mi * 16 + (lane >> 2);
            int n = wn * 32 + nf * 8 + (lane & 3) * 2;
            sOut[m * OS + n]           = acc[mi][nf][0];
            sOut[m * OS + n + 1]       = acc[mi][nf][1];
            sOut[(m + 8) * OS + n]     = acc[mi][nf][2];
            sOut[(m + 8) * OS + n + 1] = acc[mi][nf][3];
        }
    __syncthreads();

    // warp w handles rows w*16 .. w*16+15; lane covers 4 cols
    const int cb = n0 + lane * 4;
    const float4 bv = *reinterpret_cast<const float4*>(bias + cb);
#pragma unroll
    for (int rr = 0; rr < 16; ++rr) {
        int row = warp * 16 + rr;
        float4 v = *reinterpret_cast<float4*>(sOut + row * OS + lane * 4);
        v.x = __expf(v.x + bv.x);
        v.y = __expf(v.y + bv.y);
        v.z = __expf(v.z + bv.z);
        v.w = __expf(v.w + bv.w);
        if (n0 == 0 && lane == 0) v.y = 0.f;   // PAD_IDX == 1
        float rsum = v.x + v.y + v.z + v.w;
#pragma unroll
        for (int o = 16; o > 0; o >>= 1)
            rsum += __shfl_xor_sync(0xffffffffu, rsum, o);
        __half2 h0 = __floats2half2_rn(v.x, v.y);
        __half2 h1 = __floats2half2_rn(v.z, v.w);
        uint2 u; u.x = *reinterpret_cast<uint32_t*>(&h0); u.y = *reinterpret_cast<uint32_t*>(&h1);
        *reinterpret_cast<uint2*>(g_E16 + (size_t)(m0 + row) * VOCAB + cb) = u;
        if (lane == 0) atomicAdd(&g_rowsum[m0 + row], rsum);
    }
}

// ============================================================
// finalize: out[row, 0:VOCAB] = e16 * (1 - p_copy)/rowsum
// ============================================================
__global__ void finalize_kernel(float* __restrict__ out) {
    long long idx = (long long)blockIdx.x * blockDim.x + threadIdx.x;  // 8-half unit
    const int W8 = VOCAB / 8;   // 4000
    int row = (int)(idx / W8);
    int c8  = (int)(idx - (long long)row * W8);
    if (row >= NROWS) return;
    float s = (1.f - g_pcopy[row]) * __frcp_rn(g_rowsum[row]);
    uint4 u = *reinterpret_cast<const uint4*>(g_E16 + (size_t)row * VOCAB + c8 * 8);
    __half2 h0 = *reinterpret_cast<__half2*>(&u.x);
    __half2 h1 = *reinterpret_cast<__half2*>(&u.y);
    __half2 h2 = *reinterpret_cast<__half2*>(&u.z);
    __half2 h3 = *reinterpret_cast<__half2*>(&u.w);
    float2 f0 = __half22float2(h0), f1 = __half22float2(h1);
    float2 f2 = __half22float2(h2), f3 = __half22float2(h3);
    float4 o0, o1;
    o0.x = f0.x * s; o0.y = f0.y * s; o0.z = f1.x * s; o0.w = f1.y * s;
    o1.x = f2.x * s; o1.y = f2.y * s; o1.z = f3.x * s; o1.w = f3.y * s;
    float* dst = out + (size_t)row * OUTC + c8 * 8;
    *reinterpret_cast<float4*>(dst)     = o0;
    *reinterpret_cast<float4*>(dst + 4) = o1;
}

// ============================================================
extern "C" void kernel_launch(void* const* d_in, const int* in_sizes, int n_in,
                              void* d_out, int out_size) {
    const float* hidden  = (const float*)d_in[0];
    const float* attn    = (const float*)d_in[1];
    const float* src_map = (const float*)d_in[2];
    const float* W       = (const float*)d_in[3];
    const float* b       = (const float*)d_in[4];
    const float* W_copy  = (const float*)d_in[5];
    const float* b_copy  = (const float*)d_in[6];
    float* out = (float*)d_out;

    cudaFuncSetAttribute(gemm_kernel, cudaFuncAttributeMaxDynamicSharedMemorySize, SMEM_BYTES);

    convW_kernel<<<32000, 256>>>(W);                                         // 0
    convH_kernel<<<2048, 256>>>(hidden);                                     // 1
    prep_kernel<<<NROWS / 8, 256>>>(hidden, W_copy, b_copy, out, (long long)out_size); // 2
    dim3 grid(NROWS / BM, VOCAB / BN);                                       // (16, 250)
    gemm_kernel<<<grid, 256, SMEM_BYTES>>>(b);                               // 3 (profiled)
    copy_kernel<<<NROWS, 128>>>(attn, src_map, out);                         // 4
    finalize_kernel<<<(NROWS * (VOCAB / 8)) / 256, 256>>>(out);              // 5
}